// round 2
// baseline (speedup 1.0000x reference)
#include <cuda_runtime.h>
#include <math.h>

// Problem constants (fixed by the dataset)
#define NB 8
#define NT 2048
#define NC 1024
#define NH 256

// Scratch for projected Q, K, V  (3 x 16 MB; __device__ globals = allowed scratch)
__device__ float g_q[NB * NT * NH];
__device__ float g_k[NB * NT * NH];
__device__ float g_v[NB * NT * NH];

// ---------------------------------------------------------------------------
// Kernel 1: QKV projection GEMM.  M = NB*NT = 16384, K = NC = 1024, N = NH = 256
// Tiles: BM=128, BN=128, BK=16. 256 threads, 8x8 micro-tile per thread.
// blockIdx.z selects which weight (0=Q,1=K,2=V).
// ---------------------------------------------------------------------------
__global__ void __launch_bounds__(256)
qkv_gemm_kernel(const float* __restrict__ x,
                const float* __restrict__ Wq,
                const float* __restrict__ Wk,
                const float* __restrict__ Wv)
{
    const int BM = 128, BN = 128, BK = 16;
    __shared__ float As[BK][BM + 4];   // A stored transposed: As[k][m]
    __shared__ float Bs[BK][BN];       // Bs[k][n]

    const int z = blockIdx.z;
    const float* W   = (z == 0) ? Wq : ((z == 1) ? Wk : Wv);
    float*       out = (z == 0) ? g_q : ((z == 1) ? g_k : g_v);

    const int m0 = blockIdx.y * BM;
    const int n0 = blockIdx.x * BN;
    const int t  = threadIdx.x;          // 0..255
    const int tr = t % 16;               // row group (8 rows each)
    const int tc = t / 16;               // col group (8 cols each)

    float acc[8][8];
    #pragma unroll
    for (int i = 0; i < 8; i++)
        #pragma unroll
        for (int j = 0; j < 8; j++) acc[i][j] = 0.f;

    for (int k0 = 0; k0 < NC; k0 += BK) {
        // Load A tile: 128x16 floats = 512 float4; 2 per thread. Transpose into As.
        #pragma unroll
        for (int i = 0; i < 2; i++) {
            int idx = t + i * 256;        // 0..511
            int row = idx >> 2;           // 0..127
            int kq  = (idx & 3) * 4;      // 0,4,8,12
            float4 v4 = *(const float4*)&x[(size_t)(m0 + row) * NC + k0 + kq];
            As[kq + 0][row] = v4.x;
            As[kq + 1][row] = v4.y;
            As[kq + 2][row] = v4.z;
            As[kq + 3][row] = v4.w;
        }
        // Load B tile: 16x128 floats = 512 float4; 2 per thread.
        #pragma unroll
        for (int i = 0; i < 2; i++) {
            int idx = t + i * 256;        // 0..511
            int row = idx >> 5;           // k: 0..15
            int col = (idx & 31) * 4;     // n: 0..124
            float4 v4 = *(const float4*)&W[(size_t)(k0 + row) * NH + n0 + col];
            *(float4*)&Bs[row][col] = v4;
        }
        __syncthreads();

        #pragma unroll
        for (int kk = 0; kk < BK; kk++) {
            float4 a0 = *(float4*)&As[kk][tr * 8];
            float4 a1 = *(float4*)&As[kk][tr * 8 + 4];
            float4 b0 = *(float4*)&Bs[kk][tc * 8];
            float4 b1 = *(float4*)&Bs[kk][tc * 8 + 4];
            float a[8] = {a0.x, a0.y, a0.z, a0.w, a1.x, a1.y, a1.z, a1.w};
            float b[8] = {b0.x, b0.y, b0.z, b0.w, b1.x, b1.y, b1.z, b1.w};
            #pragma unroll
            for (int i = 0; i < 8; i++)
                #pragma unroll
                for (int j = 0; j < 8; j++)
                    acc[i][j] += a[i] * b[j];
        }
        __syncthreads();
    }

    // Write back: each thread 8 rows x 8 cols (two float4 per row)
    #pragma unroll
    for (int i = 0; i < 8; i++) {
        int row = m0 + tr * 8 + i;
        float* op = &out[(size_t)row * NH + n0 + tc * 8];
        *(float4*)&op[0] = make_float4(acc[i][0], acc[i][1], acc[i][2], acc[i][3]);
        *(float4*)&op[4] = make_float4(acc[i][4], acc[i][5], acc[i][6], acc[i][7]);
    }
}

// ---------------------------------------------------------------------------
// Kernel 2: causal flash attention, fp32.
// Per CTA: 64 query rows (full H=256), stream key tiles of 64.
// Smem: Qs transposed [256][68], KV buffer (K transposed [256][68] then V
// row-major [64][256]), S/P [64][65], stats.
// Grid: (T/64, B) = (32, 8); 256 threads.
// ---------------------------------------------------------------------------
#define TQ 64
#define TS 64
#define QK_STRIDE 68          // padded r/s stride for transposed layouts
#define S_STRIDE  65

#define SM_FLOATS (NH * QK_STRIDE /*Qs*/ + NH * QK_STRIDE /*KV*/ + TQ * S_STRIDE /*S*/ \
                   + TQ /*m*/ + TQ /*l*/ + TQ /*alpha*/ + 256 /*red*/)
#define SM_BYTES  (SM_FLOATS * 4)

__global__ void __launch_bounds__(256)
attn_flash_kernel(float* __restrict__ out)
{
    extern __shared__ float sm[];
    float* Qs   = sm;                                  // [NH][QK_STRIDE]
    float* KV   = Qs + NH * QK_STRIDE;                 // Ks [NH][QK_STRIDE] or V [TS][NH]
    float* S    = KV + NH * QK_STRIDE;                 // [TQ][S_STRIDE]
    float* mrow = S + TQ * S_STRIDE;                   // [TQ]
    float* lrow = mrow + TQ;                           // [TQ]
    float* arow = lrow + TQ;                           // [TQ]
    float* red  = arow + TQ;                           // [256]

    const int b  = blockIdx.y;
    const int q0 = blockIdx.x * TQ;
    const int t  = threadIdx.x;

    const float* qg = g_q + ((size_t)b * NT + q0) * NH;
    const float* kg = g_k + (size_t)b * NT * NH;
    const float* vg = g_v + (size_t)b * NT * NH;

    // Load Q tile transposed: Qs[h][r]
    for (int idx = t; idx < TQ * NH; idx += 256) {
        int r = idx / NH, h = idx % NH;                // coalesced gmem read
        Qs[h * QK_STRIDE + r] = qg[idx];
    }
    if (t < TQ) { mrow[t] = -1e30f; lrow[t] = 0.f; arow[t] = 1.f; }

    // Output accumulator: thread owns row r_own = t/4, cols 4*cq + 16*j + 0..3
    const int r_own = t >> 2;          // 0..63
    const int cq    = t & 3;           // 0..3
    float O[64];
    #pragma unroll
    for (int i = 0; i < 64; i++) O[i] = 0.f;

    // S-compute mapping: 16x16 thread grid, 4x4 micro-tile
    const int tr = t % 16;             // S rows tr*4..+3
    const int tc = t / 16;             // S cols tc*4..+3

    const int ntiles = q0 / TS + 1;    // causal: key tiles 0..diagonal
    for (int tile = 0; tile < ntiles; tile++) {
        const int s0 = tile * TS;

        __syncthreads();  // prior PV reads of KV done before overwrite
        // Load K tile transposed: Ks[h][s]
        for (int idx = t; idx < TS * NH; idx += 256) {
            int s = idx / NH, h = idx % NH;
            KV[h * QK_STRIDE + s] = kg[(size_t)(s0 + s) * NH + h];
        }
        __syncthreads();

        // S = Q K^T * 16, masked
        {
            float acc[4][4];
            #pragma unroll
            for (int i = 0; i < 4; i++)
                #pragma unroll
                for (int j = 0; j < 4; j++) acc[i][j] = 0.f;

            #pragma unroll 8
            for (int k = 0; k < NH; k++) {
                float4 a4 = *(float4*)&Qs[k * QK_STRIDE + tr * 4];
                float4 c4 = *(float4*)&KV[k * QK_STRIDE + tc * 4];
                float av[4] = {a4.x, a4.y, a4.z, a4.w};
                float cv[4] = {c4.x, c4.y, c4.z, c4.w};
                #pragma unroll
                for (int i = 0; i < 4; i++)
                    #pragma unroll
                    for (int j = 0; j < 4; j++)
                        acc[i][j] += av[i] * cv[j];
            }
            #pragma unroll
            for (int i = 0; i < 4; i++) {
                int r = tr * 4 + i;
                #pragma unroll
                for (int j = 0; j < 4; j++) {
                    int s = tc * 4 + j;
                    float v = acc[i][j] * 16.0f;                 // * sqrt(H)
                    if (s0 + s > q0 + r) v = -3.0e38f;           // causal mask
                    S[r * S_STRIDE + s] = v;
                }
            }
        }
        __syncthreads();

        // Load V tile (row-major, overwrites Ks) — K reads are fenced above.
        for (int idx = t; idx < TS * NH; idx += 256) {
            KV[idx] = vg[(size_t)s0 * NH + idx];
        }
        // Partial row max: thread (r_own, cq) scans 16 scores
        {
            float pm = -3.0e38f;
            #pragma unroll
            for (int s = cq * 16; s < cq * 16 + 16; s++)
                pm = fmaxf(pm, S[r_own * S_STRIDE + s]);
            red[cq * 64 + r_own] = pm;
        }
        __syncthreads();

        if (t < TQ) {
            float m_old = mrow[t];
            float m_new = fmaxf(m_old,
                          fmaxf(fmaxf(red[t], red[64 + t]),
                                fmaxf(red[128 + t], red[192 + t])));
            float al = __expf(m_old - m_new);    // == 1 when unchanged
            mrow[t] = m_new;
            arow[t] = al;
            lrow[t] *= al;
        }
        __syncthreads();

        // Exponentiate in place + partial sums
        {
            float m_new = mrow[r_own];
            float psum = 0.f;
            #pragma unroll
            for (int s = cq * 16; s < cq * 16 + 16; s++) {
                float p = __expf(S[r_own * S_STRIDE + s] - m_new);
                S[r_own * S_STRIDE + s] = p;
                psum += p;
            }
            red[cq * 64 + r_own] = psum;
        }
        __syncthreads();

        if (t < TQ)
            lrow[t] += red[t] + red[64 + t] + red[128 + t] + red[192 + t];

        // PV accumulate: O = O*alpha + P @ V
        {
            float al = arow[r_own];
            #pragma unroll
            for (int j = 0; j < 64; j++) O[j] *= al;
            #pragma unroll 4
            for (int s = 0; s < TS; s++) {
                float p = S[r_own * S_STRIDE + s];
                const float* vrow = &KV[s * NH];
                #pragma unroll
                for (int j = 0; j < 16; j++) {
                    float4 v4 = *(const float4*)&vrow[4 * cq + 16 * j];
                    O[4 * j + 0] += p * v4.x;
                    O[4 * j + 1] += p * v4.y;
                    O[4 * j + 2] += p * v4.z;
                    O[4 * j + 3] += p * v4.w;
                }
            }
        }
    }

    __syncthreads();   // make final lrow visible to all readers of row r_own
    {
        float inv = 1.0f / lrow[r_own];
        float* og = out + ((size_t)b * NT + q0 + r_own) * NH;
        #pragma unroll
        for (int j = 0; j < 16; j++) {
            float4 v4 = make_float4(O[4 * j] * inv, O[4 * j + 1] * inv,
                                    O[4 * j + 2] * inv, O[4 * j + 3] * inv);
            *(float4*)&og[4 * cq + 16 * j] = v4;
        }
    }
}

// ---------------------------------------------------------------------------
extern "C" void kernel_launch(void* const* d_in, const int* in_sizes, int n_in,
                              void* d_out, int out_size)
{
    const float* x  = (const float*)d_in[0];
    const float* Wq = (const float*)d_in[1];
    const float* Wk = (const float*)d_in[2];
    const float* Wv = (const float*)d_in[3];
    float* out = (float*)d_out;

    cudaFuncSetAttribute(attn_flash_kernel,
                         cudaFuncAttributeMaxDynamicSharedMemorySize, SM_BYTES);

    // QKV projection: grid (N/128, M/128, 3)
    qkv_gemm_kernel<<<dim3(NH / 128, (NB * NT) / 128, 3), 256>>>(x, Wq, Wk, Wv);

    // Flash attention: grid (T/64, B)
    attn_flash_kernel<<<dim3(NT / TQ, NB), 256, SM_BYTES>>>(out);
}

// round 5
// speedup vs baseline: 2.3396x; 2.3396x over previous
#include <cuda_runtime.h>
#include <cuda_bf16.h>
#include <cstdint>

// Problem constants
#define NB 8
#define NT 2048
#define NC 1024
#define NH 256

// Split-bf16 projected tensors (hi + lo). q is pre-scaled by 16 (= sqrt(H)).
__device__ __nv_bfloat16 g_qhi[NB*NT*NH], g_qlo[NB*NT*NH];
__device__ __nv_bfloat16 g_khi[NB*NT*NH], g_klo[NB*NT*NH];
__device__ __nv_bfloat16 g_vhi[NB*NT*NH], g_vlo[NB*NT*NH];

__device__ __forceinline__ uint32_t smem_u32(const void* p) {
    uint32_t a;
    asm("{ .reg .u64 t; cvta.to.shared.u64 t, %1; cvt.u32.u64 %0, t; }"
        : "=r"(a) : "l"(p));
    return a;
}
__device__ __forceinline__ void ldmx4(uint32_t* r, uint32_t addr) {
    asm volatile("ldmatrix.sync.aligned.m8n8.x4.shared.b16 {%0,%1,%2,%3}, [%4];"
        : "=r"(r[0]), "=r"(r[1]), "=r"(r[2]), "=r"(r[3]) : "r"(addr));
}
__device__ __forceinline__ void ldmx4t(uint32_t* r, uint32_t addr) {
    asm volatile("ldmatrix.sync.aligned.m8n8.x4.trans.shared.b16 {%0,%1,%2,%3}, [%4];"
        : "=r"(r[0]), "=r"(r[1]), "=r"(r[2]), "=r"(r[3]) : "r"(addr));
}
__device__ __forceinline__ void mma_bf16(float* c, const uint32_t* a, const uint32_t* b) {
    asm volatile("mma.sync.aligned.m16n8k16.row.col.f32.bf16.bf16.f32 "
        "{%0,%1,%2,%3}, {%4,%5,%6,%7}, {%8,%9}, {%0,%1,%2,%3};"
        : "+f"(c[0]), "+f"(c[1]), "+f"(c[2]), "+f"(c[3])
        : "r"(a[0]), "r"(a[1]), "r"(a[2]), "r"(a[3]), "r"(b[0]), "r"(b[1]));
}
__device__ __forceinline__ uint32_t packbb(__nv_bfloat16 a, __nv_bfloat16 b) {
    unsigned short ua = *reinterpret_cast<unsigned short*>(&a);
    unsigned short ub = *reinterpret_cast<unsigned short*>(&b);
    return (uint32_t)ua | ((uint32_t)ub << 16);
}

// ---------------------------------------------------------------------------
// Kernel 1: QKV projection GEMM (fp32 math), epilogue emits split-bf16 hi/lo.
// ---------------------------------------------------------------------------
__global__ void __launch_bounds__(256)
qkv_gemm_kernel(const float* __restrict__ x,
                const float* __restrict__ Wq,
                const float* __restrict__ Wk,
                const float* __restrict__ Wv)
{
    const int BM = 128, BN = 128, BK = 16;
    __shared__ float As[BK][BM + 4];
    __shared__ float Bs[BK][BN];

    const int z = blockIdx.z;
    const float* W = (z == 0) ? Wq : ((z == 1) ? Wk : Wv);
    __nv_bfloat16* ohi = (z == 0) ? g_qhi : ((z == 1) ? g_khi : g_vhi);
    __nv_bfloat16* olo = (z == 0) ? g_qlo : ((z == 1) ? g_klo : g_vlo);
    const float scale = (z == 0) ? 16.0f : 1.0f;   // fold sqrt(H) into q

    const int m0 = blockIdx.y * BM;
    const int n0 = blockIdx.x * BN;
    const int t  = threadIdx.x;
    const int tr = t % 16;
    const int tc = t / 16;

    float acc[8][8];
    #pragma unroll
    for (int i = 0; i < 8; i++)
        #pragma unroll
        for (int j = 0; j < 8; j++) acc[i][j] = 0.f;

    for (int k0 = 0; k0 < NC; k0 += BK) {
        #pragma unroll
        for (int i = 0; i < 2; i++) {
            int idx = t + i * 256;
            int row = idx >> 2;
            int kq  = (idx & 3) * 4;
            float4 v4 = *(const float4*)&x[(size_t)(m0 + row) * NC + k0 + kq];
            As[kq + 0][row] = v4.x; As[kq + 1][row] = v4.y;
            As[kq + 2][row] = v4.z; As[kq + 3][row] = v4.w;
        }
        #pragma unroll
        for (int i = 0; i < 2; i++) {
            int idx = t + i * 256;
            int row = idx >> 5;
            int col = (idx & 31) * 4;
            *(float4*)&Bs[row][col] = *(const float4*)&W[(size_t)(k0 + row) * NH + n0 + col];
        }
        __syncthreads();

        #pragma unroll
        for (int kk = 0; kk < BK; kk++) {
            float4 a0 = *(float4*)&As[kk][tr * 8];
            float4 a1 = *(float4*)&As[kk][tr * 8 + 4];
            float4 b0 = *(float4*)&Bs[kk][tc * 8];
            float4 b1 = *(float4*)&Bs[kk][tc * 8 + 4];
            float a[8] = {a0.x, a0.y, a0.z, a0.w, a1.x, a1.y, a1.z, a1.w};
            float b[8] = {b0.x, b0.y, b0.z, b0.w, b1.x, b1.y, b1.z, b1.w};
            #pragma unroll
            for (int i = 0; i < 8; i++)
                #pragma unroll
                for (int j = 0; j < 8; j++)
                    acc[i][j] += a[i] * b[j];
        }
        __syncthreads();
    }

    #pragma unroll
    for (int i = 0; i < 8; i++) {
        int row = m0 + tr * 8 + i;
        size_t base = (size_t)row * NH + n0 + tc * 8;
        uint32_t hw[4], lw[4];
        #pragma unroll
        for (int j2 = 0; j2 < 4; j2++) {
            float v0 = acc[i][2 * j2]     * scale;
            float v1 = acc[i][2 * j2 + 1] * scale;
            __nv_bfloat16 h0 = __float2bfloat16(v0);
            __nv_bfloat16 h1 = __float2bfloat16(v1);
            __nv_bfloat16 l0 = __float2bfloat16(v0 - __bfloat162float(h0));
            __nv_bfloat16 l1 = __float2bfloat16(v1 - __bfloat162float(h1));
            hw[j2] = packbb(h0, h1);
            lw[j2] = packbb(l0, l1);
        }
        *(uint4*)&ohi[base] = make_uint4(hw[0], hw[1], hw[2], hw[3]);
        *(uint4*)&olo[base] = make_uint4(lw[0], lw[1], lw[2], lw[3]);
    }
}

// ---------------------------------------------------------------------------
// Kernel 2: mma.sync flash attention, split-bf16, online softmax.
// 256 threads = 8 warps in a 4(row) x 2(col) grid. TQ=TS=64, H=256.
// ---------------------------------------------------------------------------
#define QSTR 264                 // bf16 elements per row (256 + 8 pad)
#define PSTR 72                  // bf16 elements per row (64 + 8 pad)
#define QROW_B (QSTR * 2)        // 528 bytes
#define PROW_B (PSTR * 2)        // 144 bytes

#define OFF_QHI 0
#define OFF_QLO (OFF_QHI + 64 * QROW_B)      // 33792
#define OFF_KH  (OFF_QLO + 64 * QROW_B)      // 67584  (K tile, later V tile)
#define OFF_KL  (OFF_KH  + 64 * QROW_B)      // 101376
#define OFF_S   (OFF_KL  + 64 * QROW_B)      // 135168  fp32 [64][65]
#define OFF_PHI (OFF_S   + 64 * 65 * 4)      // 151808  bf16 [64][72]
#define OFF_PLO (OFF_PHI + 64 * PROW_B)      // 161024
#define OFF_ST  (OFF_PLO + 64 * PROW_B)      // 170240  mrow/lrow/arow/red
#define ATTN_SMEM (OFF_ST + (64 + 64 + 64 + 256) * 4)   // 172032

// Load one [64 rows][256 bf16] gmem tile (row stride NH) into smem stride QSTR.
__device__ __forceinline__ void load_tile64(char* smp, int off,
                                            const __nv_bfloat16* g, int t) {
    #pragma unroll
    for (int i = 0; i < 8; i++) {
        int idx = t + i * 256;
        int row = idx >> 5, seg = idx & 31;
        uint4 v = *reinterpret_cast<const uint4*>(g + (size_t)row * NH + seg * 8);
        *reinterpret_cast<uint4*>(smp + off + row * QROW_B + seg * 16) = v;
    }
}

__global__ void __launch_bounds__(256, 1)
attn_mma_kernel(float* __restrict__ out)
{
    extern __shared__ char smp[];
    const uint32_t sb = smem_u32(smp);
    float* Sm   = (float*)(smp + OFF_S);
    float* mrow = (float*)(smp + OFF_ST);
    float* lrow = mrow + 64;
    float* arow = lrow + 64;
    float* red  = arow + 64;

    const int t   = threadIdx.x;
    const int wid = t >> 5;
    const int l   = t & 31;
    const int wr  = wid & 3;          // warp row block (16 rows)
    const int wc  = wid >> 2;         // warp col block
    const int b   = blockIdx.y;
    const int q0  = blockIdx.x * 64;

    // Load Q tile (hi+lo)
    load_tile64(smp, OFF_QHI, g_qhi + ((size_t)b * NT + q0) * NH, t);
    load_tile64(smp, OFF_QLO, g_qlo + ((size_t)b * NT + q0) * NH, t);
    if (t < 64) { mrow[t] = -1e30f; lrow[t] = 0.f; arow[t] = 0.f; }

    const __nv_bfloat16* kh = g_khi + (size_t)b * NT * NH;
    const __nv_bfloat16* kl = g_klo + (size_t)b * NT * NH;
    const __nv_bfloat16* vh = g_vhi + (size_t)b * NT * NH;
    const __nv_bfloat16* vl = g_vlo + (size_t)b * NT * NH;

    float oacc[16][4];
    #pragma unroll
    for (int i = 0; i < 16; i++)
        #pragma unroll
        for (int j = 0; j < 4; j++) oacc[i][j] = 0.f;

    // softmax worker mapping: 4 threads per row
    const int rr = t >> 2;            // 0..63
    const int q4 = t & 3;             // 0..3
    // mma lane decomposition
    const int lg = l >> 2;            // group id 0..7
    const int lt = l & 3;             // thread-in-group

    const int ntiles = q0 / 64 + 1;
    for (int tile = 0; tile < ntiles; tile++) {
        const int s0 = tile * 64;

        __syncthreads();   // prior tile's PV reads of KV/P done
        load_tile64(smp, OFF_KH, kh + (size_t)s0 * NH, t);
        load_tile64(smp, OFF_KL, kl + (size_t)s0 * NH, t);
        __syncthreads();

        // ---- S = Qhi*Khi + Qhi*Klo + Qlo*Khi  (warp: rows 16wr, cols 32wc)
        float sacc[4][4];
        #pragma unroll
        for (int i = 0; i < 4; i++)
            #pragma unroll
            for (int j = 0; j < 4; j++) sacc[i][j] = 0.f;

        #pragma unroll 4
        for (int kk = 0; kk < 16; kk++) {
            const int k = kk * 16;
            uint32_t aH[4], aL[4];
            uint32_t qa = sb + OFF_QHI + (16 * wr + (l & 15)) * QROW_B
                        + (k + ((l >> 4) << 3)) * 2;
            ldmx4(aH, qa);
            ldmx4(aL, qa + (OFF_QLO - OFF_QHI));
            #pragma unroll
            for (int np = 0; np < 2; np++) {
                const int n0 = 32 * wc + 16 * np;
                uint32_t ka = sb + OFF_KH
                            + (n0 + (l & 7) + ((l >> 4) << 3)) * QROW_B
                            + (k + (((l >> 3) & 1) << 3)) * 2;
                uint32_t bH[4], bL[4];
                ldmx4(bH, ka);
                ldmx4(bL, ka + (OFF_KL - OFF_KH));
                mma_bf16(sacc[2 * np],     aH, bH);
                mma_bf16(sacc[2 * np + 1], aH, bH + 2);
                mma_bf16(sacc[2 * np],     aH, bL);
                mma_bf16(sacc[2 * np + 1], aH, bL + 2);
                mma_bf16(sacc[2 * np],     aL, bH);
                mma_bf16(sacc[2 * np + 1], aL, bH + 2);
            }
        }

        // store S with causal mask
        #pragma unroll
        for (int nb = 0; nb < 4; nb++) {
            int col = 32 * wc + 8 * nb + 2 * lt;
            int r0  = 16 * wr + lg;
            Sm[r0 * 65 + col]     = (s0 + col     <= q0 + r0) ? sacc[nb][0] : -3.0e38f;
            Sm[r0 * 65 + col + 1] = (s0 + col + 1 <= q0 + r0) ? sacc[nb][1] : -3.0e38f;
            int r1 = r0 + 8;
            Sm[r1 * 65 + col]     = (s0 + col     <= q0 + r1) ? sacc[nb][2] : -3.0e38f;
            Sm[r1 * 65 + col + 1] = (s0 + col + 1 <= q0 + r1) ? sacc[nb][3] : -3.0e38f;
        }
        __syncthreads();

        // ---- overwrite K buffer with V tile (hi+lo); published by sync below
        load_tile64(smp, OFF_KH, vh + (size_t)s0 * NH, t);
        load_tile64(smp, OFF_KL, vl + (size_t)s0 * NH, t);

        // ---- row max partials
        {
            float pm = -3.0e38f;
            #pragma unroll
            for (int c = q4 * 16; c < q4 * 16 + 16; c++)
                pm = fmaxf(pm, Sm[rr * 65 + c]);
            red[q4 * 64 + rr] = pm;
        }
        __syncthreads();
        if (t < 64) {
            float m_old = mrow[t];
            float m_new = fmaxf(m_old,
                          fmaxf(fmaxf(red[t], red[64 + t]),
                                fmaxf(red[128 + t], red[192 + t])));
            float al = __expf(m_old - m_new);
            mrow[t] = m_new; arow[t] = al; lrow[t] *= al;
        }
        __syncthreads();

        // ---- P = exp(S - m): write bf16 hi/lo tiles + row-sum partials
        {
            float mn = mrow[rr];
            float ps = 0.f;
            __nv_bfloat16* Ph = (__nv_bfloat16*)(smp + OFF_PHI) + rr * PSTR;
            __nv_bfloat16* Pl = (__nv_bfloat16*)(smp + OFF_PLO) + rr * PSTR;
            #pragma unroll
            for (int c = q4 * 16; c < q4 * 16 + 16; c++) {
                float p = __expf(Sm[rr * 65 + c] - mn);
                ps += p;
                __nv_bfloat16 h = __float2bfloat16(p);
                Ph[c] = h;
                Pl[c] = __float2bfloat16(p - __bfloat162float(h));
            }
            red[q4 * 64 + rr] = ps;
        }
        __syncthreads();
        if (t < 64)
            lrow[t] += red[t] + red[64 + t] + red[128 + t] + red[192 + t];

        // ---- rescale O accumulators by alpha (per row)
        {
            float a0 = arow[16 * wr + lg];
            float a1 = arow[16 * wr + 8 + lg];
            #pragma unroll
            for (int nb = 0; nb < 16; nb++) {
                oacc[nb][0] *= a0; oacc[nb][1] *= a0;
                oacc[nb][2] *= a1; oacc[nb][3] *= a1;
            }
        }
        __syncthreads();   // publish V tile + P tiles

        // ---- O += Phi*Vhi + Phi*Vlo + Plo*Vhi  (warp: rows 16wr, cols 128wc)
        #pragma unroll
        for (int ks = 0; ks < 4; ks++) {
            const int s = 16 * ks;
            uint32_t aH[4], aL[4];
            uint32_t pa = sb + OFF_PHI + (16 * wr + (l & 15)) * PROW_B
                        + (s + ((l >> 4) << 3)) * 2;
            ldmx4(aH, pa);
            ldmx4(aL, pa + (OFF_PLO - OFF_PHI));
            #pragma unroll
            for (int nb = 0; nb < 8; nb++) {
                const int h0 = 128 * wc + 16 * nb;
                uint32_t va = sb + OFF_KH
                            + (s + (l & 7) + (((l >> 3) & 1) << 3)) * QROW_B
                            + (h0 + ((l >> 4) << 3)) * 2;
                uint32_t bH[4], bL[4];
                ldmx4t(bH, va);
                ldmx4t(bL, va + (OFF_KL - OFF_KH));
                mma_bf16(oacc[2 * nb],     aH, bH);
                mma_bf16(oacc[2 * nb + 1], aH, bH + 2);
                mma_bf16(oacc[2 * nb],     aH, bL);
                mma_bf16(oacc[2 * nb + 1], aH, bL + 2);
                mma_bf16(oacc[2 * nb],     aL, bH);
                mma_bf16(oacc[2 * nb + 1], aL, bH + 2);
            }
        }
    }

    // ---- epilogue: out = O / l
    __syncthreads();
    {
        int g0 = 16 * wr + lg;
        int g1 = g0 + 8;
        float inv0 = 1.0f / lrow[g0];
        float inv1 = 1.0f / lrow[g1];
        float* o0 = out + ((size_t)b * NT + q0 + g0) * NH;
        float* o1 = out + ((size_t)b * NT + q0 + g1) * NH;
        #pragma unroll
        for (int nb = 0; nb < 16; nb++) {
            int col = 128 * wc + 8 * nb + 2 * lt;
            *(float2*)&o0[col] = make_float2(oacc[nb][0] * inv0, oacc[nb][1] * inv0);
            *(float2*)&o1[col] = make_float2(oacc[nb][2] * inv1, oacc[nb][3] * inv1);
        }
    }
}

// ---------------------------------------------------------------------------
extern "C" void kernel_launch(void* const* d_in, const int* in_sizes, int n_in,
                              void* d_out, int out_size)
{
    const float* x  = (const float*)d_in[0];
    const float* Wq = (const float*)d_in[1];
    const float* Wk = (const float*)d_in[2];
    const float* Wv = (const float*)d_in[3];
    float* out = (float*)d_out;

    cudaFuncSetAttribute(attn_mma_kernel,
                         cudaFuncAttributeMaxDynamicSharedMemorySize, ATTN_SMEM);

    qkv_gemm_kernel<<<dim3(NH / 128, (NB * NT) / 128, 3), 256>>>(x, Wq, Wk, Wv);
    attn_mma_kernel<<<dim3(NT / 64, NB), 256, ATTN_SMEM>>>(out);
}

// round 6
// speedup vs baseline: 3.3130x; 1.4161x over previous
#include <cuda_runtime.h>
#include <cuda_bf16.h>
#include <cstdint>

// Problem constants
#define NB 8
#define NT 2048
#define NC 1024
#define NH 256

// Split-bf16 projected tensors (hi + lo). q is pre-scaled by 16 (= sqrt(H)).
__device__ __nv_bfloat16 g_qhi[NB*NT*NH], g_qlo[NB*NT*NH];
__device__ __nv_bfloat16 g_khi[NB*NT*NH], g_klo[NB*NT*NH];
__device__ __nv_bfloat16 g_vhi[NB*NT*NH], g_vlo[NB*NT*NH];

__device__ __forceinline__ uint32_t smem_u32(const void* p) {
    uint32_t a;
    asm("{ .reg .u64 t; cvta.to.shared.u64 t, %1; cvt.u32.u64 %0, t; }"
        : "=r"(a) : "l"(p));
    return a;
}
__device__ __forceinline__ void ldmx4(uint32_t* r, uint32_t addr) {
    asm volatile("ldmatrix.sync.aligned.m8n8.x4.shared.b16 {%0,%1,%2,%3}, [%4];"
        : "=r"(r[0]), "=r"(r[1]), "=r"(r[2]), "=r"(r[3]) : "r"(addr));
}
__device__ __forceinline__ void ldmx4t(uint32_t* r, uint32_t addr) {
    asm volatile("ldmatrix.sync.aligned.m8n8.x4.trans.shared.b16 {%0,%1,%2,%3}, [%4];"
        : "=r"(r[0]), "=r"(r[1]), "=r"(r[2]), "=r"(r[3]) : "r"(addr));
}
__device__ __forceinline__ void mma_bf16(float* c, const uint32_t* a, const uint32_t* b) {
    asm volatile("mma.sync.aligned.m16n8k16.row.col.f32.bf16.bf16.f32 "
        "{%0,%1,%2,%3}, {%4,%5,%6,%7}, {%8,%9}, {%0,%1,%2,%3};"
        : "+f"(c[0]), "+f"(c[1]), "+f"(c[2]), "+f"(c[3])
        : "r"(a[0]), "r"(a[1]), "r"(a[2]), "r"(a[3]), "r"(b[0]), "r"(b[1]));
}
__device__ __forceinline__ uint32_t packbb(__nv_bfloat16 a, __nv_bfloat16 b) {
    unsigned short ua = *reinterpret_cast<unsigned short*>(&a);
    unsigned short ub = *reinterpret_cast<unsigned short*>(&b);
    return (uint32_t)ua | ((uint32_t)ub << 16);
}
__device__ __forceinline__ void split2(float v0, float v1, uint32_t& hw, uint32_t& lw) {
    __nv_bfloat16 h0 = __float2bfloat16(v0);
    __nv_bfloat16 h1 = __float2bfloat16(v1);
    __nv_bfloat16 l0 = __float2bfloat16(v0 - __bfloat162float(h0));
    __nv_bfloat16 l1 = __float2bfloat16(v1 - __bfloat162float(h1));
    hw = packbb(h0, h1);
    lw = packbb(l0, l1);
}

// ---------------------------------------------------------------------------
// Kernel 1: QKV projection GEMM, split-bf16 mma.sync.
// M=16384, N=128 per CTA (2 n-CTAs), K=1024, BK=32. 256 threads.
// Warp grid 2(m)x4(n): warp tile 64x32. 3-term split: AhBh + AhBl + AlBh.
// ---------------------------------------------------------------------------
#define ASTR 40      // bf16 stride of A smem row (32 + 8 pad)
#define WSTR 136     // bf16 stride of W smem row (128 + 8 pad)

__global__ void __launch_bounds__(256, 1)
qkv_gemm_kernel(const float* __restrict__ x,
                const float* __restrict__ Wq,
                const float* __restrict__ Wk,
                const float* __restrict__ Wv)
{
    __shared__ __nv_bfloat16 Ah[128][ASTR], Al[128][ASTR];
    __shared__ __nv_bfloat16 Wh[32][WSTR],  Wl[32][WSTR];

    const int z = blockIdx.z;
    const float* Wg = (z == 0) ? Wq : ((z == 1) ? Wk : Wv);
    __nv_bfloat16* ohi = (z == 0) ? g_qhi : ((z == 1) ? g_khi : g_vhi);
    __nv_bfloat16* olo = (z == 0) ? g_qlo : ((z == 1) ? g_klo : g_vlo);
    const float scale = (z == 0) ? 16.0f : 1.0f;   // fold sqrt(H) into q

    const int m0 = blockIdx.y * 128;
    const int n0 = blockIdx.x * 128;
    const int t  = threadIdx.x;
    const int l  = t & 31;
    const int wid = t >> 5;
    const int wm = wid & 1;           // 0..1 -> 64 rows
    const int wn = wid >> 1;          // 0..3 -> 32 cols
    const int lg = l >> 2;
    const int lt = l & 3;

    const uint32_t sAh = smem_u32(Ah), sAl = smem_u32(Al);
    const uint32_t sWh = smem_u32(Wh), sWl = smem_u32(Wl);

    float acc[4][4][4];
    #pragma unroll
    for (int i = 0; i < 4; i++)
        #pragma unroll
        for (int j = 0; j < 4; j++)
            #pragma unroll
            for (int k = 0; k < 4; k++) acc[i][j][k] = 0.f;

    float4 pa[4], pw[4];

    // prefetch tile 0
    #pragma unroll
    for (int i = 0; i < 4; i++) {
        int idx = t + 256 * i;
        pa[i] = *(const float4*)&x[(size_t)(m0 + (idx >> 3)) * NC + 4 * (idx & 7)];
        pw[i] = *(const float4*)&Wg[(size_t)(idx >> 5) * NH + n0 + 4 * (idx & 31)];
    }

    for (int it = 0; it < 32; it++) {
        // convert prefetched tile into smem
        #pragma unroll
        for (int i = 0; i < 4; i++) {
            int idx = t + 256 * i;
            {
                int r = idx >> 3, c = 4 * (idx & 7);
                uint32_t h01, l01, h23, l23;
                split2(pa[i].x, pa[i].y, h01, l01);
                split2(pa[i].z, pa[i].w, h23, l23);
                *(uint2*)&Ah[r][c] = make_uint2(h01, h23);
                *(uint2*)&Al[r][c] = make_uint2(l01, l23);
            }
            {
                int r = idx >> 5, c = 4 * (idx & 31);
                uint32_t h01, l01, h23, l23;
                split2(pw[i].x, pw[i].y, h01, l01);
                split2(pw[i].z, pw[i].w, h23, l23);
                *(uint2*)&Wh[r][c] = make_uint2(h01, h23);
                *(uint2*)&Wl[r][c] = make_uint2(l01, l23);
            }
        }
        __syncthreads();

        // prefetch next tile
        if (it + 1 < 32) {
            const int k0 = (it + 1) * 32;
            #pragma unroll
            for (int i = 0; i < 4; i++) {
                int idx = t + 256 * i;
                pa[i] = *(const float4*)&x[(size_t)(m0 + (idx >> 3)) * NC + k0 + 4 * (idx & 7)];
                pw[i] = *(const float4*)&Wg[(size_t)(k0 + (idx >> 5)) * NH + n0 + 4 * (idx & 31)];
            }
        }

        // mma over the 2 k16 steps
        #pragma unroll
        for (int ks = 0; ks < 2; ks++) {
            const int k = 16 * ks;
            uint32_t aH[4][4], aL[4][4];
            #pragma unroll
            for (int mi = 0; mi < 4; mi++) {
                uint32_t aa = sAh + ((64 * wm + 16 * mi + (l & 15)) * ASTR
                            + k + ((l >> 4) << 3)) * 2;
                ldmx4(aH[mi], aa);
                ldmx4(aL[mi], aa + (sAl - sAh));
            }
            #pragma unroll
            for (int nj = 0; nj < 2; nj++) {
                uint32_t wa = sWh + ((k + (l & 7) + (((l >> 3) & 1) << 3)) * WSTR
                            + 32 * wn + 16 * nj + ((l >> 4) << 3)) * 2;
                uint32_t bH[4], bL[4];
                ldmx4t(bH, wa);
                ldmx4t(bL, wa + (sWl - sWh));
                #pragma unroll
                for (int mi = 0; mi < 4; mi++) {
                    mma_bf16(acc[mi][2 * nj],     aH[mi], bH);
                    mma_bf16(acc[mi][2 * nj + 1], aH[mi], bH + 2);
                    mma_bf16(acc[mi][2 * nj],     aH[mi], bL);
                    mma_bf16(acc[mi][2 * nj + 1], aH[mi], bL + 2);
                    mma_bf16(acc[mi][2 * nj],     aL[mi], bH);
                    mma_bf16(acc[mi][2 * nj + 1], aL[mi], bH + 2);
                }
            }
        }
        __syncthreads();
    }

    // epilogue: split to hi/lo bf16, q scaled by 16
    #pragma unroll
    for (int mi = 0; mi < 4; mi++) {
        #pragma unroll
        for (int ni = 0; ni < 4; ni++) {
            int col = n0 + 32 * wn + 8 * ni + 2 * lt;
            size_t r0 = (size_t)(m0 + 64 * wm + 16 * mi + lg) * NH + col;
            size_t r1 = r0 + 8 * NH;
            uint32_t hw, lw;
            split2(acc[mi][ni][0] * scale, acc[mi][ni][1] * scale, hw, lw);
            *(uint32_t*)&ohi[r0] = hw;
            *(uint32_t*)&olo[r0] = lw;
            split2(acc[mi][ni][2] * scale, acc[mi][ni][3] * scale, hw, lw);
            *(uint32_t*)&ohi[r1] = hw;
            *(uint32_t*)&olo[r1] = lw;
        }
    }
}

// ---------------------------------------------------------------------------
// Kernel 2: mma.sync flash attention, split-bf16, online softmax.
// (unchanged from R5 — measured 370us, tensor=26%)
// 256 threads = 8 warps in a 4(row) x 2(col) grid. TQ=TS=64, H=256.
// ---------------------------------------------------------------------------
#define QSTR 264
#define PSTR 72
#define QROW_B (QSTR * 2)
#define PROW_B (PSTR * 2)

#define OFF_QHI 0
#define OFF_QLO (OFF_QHI + 64 * QROW_B)
#define OFF_KH  (OFF_QLO + 64 * QROW_B)
#define OFF_KL  (OFF_KH  + 64 * QROW_B)
#define OFF_S   (OFF_KL  + 64 * QROW_B)
#define OFF_PHI (OFF_S   + 64 * 65 * 4)
#define OFF_PLO (OFF_PHI + 64 * PROW_B)
#define OFF_ST  (OFF_PLO + 64 * PROW_B)
#define ATTN_SMEM (OFF_ST + (64 + 64 + 64 + 256) * 4)

__device__ __forceinline__ void load_tile64(char* smp, int off,
                                            const __nv_bfloat16* g, int t) {
    #pragma unroll
    for (int i = 0; i < 8; i++) {
        int idx = t + i * 256;
        int row = idx >> 5, seg = idx & 31;
        uint4 v = *reinterpret_cast<const uint4*>(g + (size_t)row * NH + seg * 8);
        *reinterpret_cast<uint4*>(smp + off + row * QROW_B + seg * 16) = v;
    }
}

__global__ void __launch_bounds__(256, 1)
attn_mma_kernel(float* __restrict__ out)
{
    extern __shared__ char smp[];
    const uint32_t sb = smem_u32(smp);
    float* Sm   = (float*)(smp + OFF_S);
    float* mrow = (float*)(smp + OFF_ST);
    float* lrow = mrow + 64;
    float* arow = lrow + 64;
    float* red  = arow + 64;

    const int t   = threadIdx.x;
    const int wid = t >> 5;
    const int l   = t & 31;
    const int wr  = wid & 3;
    const int wc  = wid >> 2;
    const int b   = blockIdx.y;
    const int q0  = blockIdx.x * 64;

    load_tile64(smp, OFF_QHI, g_qhi + ((size_t)b * NT + q0) * NH, t);
    load_tile64(smp, OFF_QLO, g_qlo + ((size_t)b * NT + q0) * NH, t);
    if (t < 64) { mrow[t] = -1e30f; lrow[t] = 0.f; arow[t] = 0.f; }

    const __nv_bfloat16* kh = g_khi + (size_t)b * NT * NH;
    const __nv_bfloat16* kl = g_klo + (size_t)b * NT * NH;
    const __nv_bfloat16* vh = g_vhi + (size_t)b * NT * NH;
    const __nv_bfloat16* vl = g_vlo + (size_t)b * NT * NH;

    float oacc[16][4];
    #pragma unroll
    for (int i = 0; i < 16; i++)
        #pragma unroll
        for (int j = 0; j < 4; j++) oacc[i][j] = 0.f;

    const int rr = t >> 2;
    const int q4 = t & 3;
    const int lg = l >> 2;
    const int lt = l & 3;

    const int ntiles = q0 / 64 + 1;
    for (int tile = 0; tile < ntiles; tile++) {
        const int s0 = tile * 64;

        __syncthreads();
        load_tile64(smp, OFF_KH, kh + (size_t)s0 * NH, t);
        load_tile64(smp, OFF_KL, kl + (size_t)s0 * NH, t);
        __syncthreads();

        float sacc[4][4];
        #pragma unroll
        for (int i = 0; i < 4; i++)
            #pragma unroll
            for (int j = 0; j < 4; j++) sacc[i][j] = 0.f;

        #pragma unroll 4
        for (int kk = 0; kk < 16; kk++) {
            const int k = kk * 16;
            uint32_t aH[4], aL[4];
            uint32_t qa = sb + OFF_QHI + (16 * wr + (l & 15)) * QROW_B
                        + (k + ((l >> 4) << 3)) * 2;
            ldmx4(aH, qa);
            ldmx4(aL, qa + (OFF_QLO - OFF_QHI));
            #pragma unroll
            for (int np = 0; np < 2; np++) {
                const int n0 = 32 * wc + 16 * np;
                uint32_t ka = sb + OFF_KH
                            + (n0 + (l & 7) + ((l >> 4) << 3)) * QROW_B
                            + (k + (((l >> 3) & 1) << 3)) * 2;
                uint32_t bH[4], bL[4];
                ldmx4(bH, ka);
                ldmx4(bL, ka + (OFF_KL - OFF_KH));
                mma_bf16(sacc[2 * np],     aH, bH);
                mma_bf16(sacc[2 * np + 1], aH, bH + 2);
                mma_bf16(sacc[2 * np],     aH, bL);
                mma_bf16(sacc[2 * np + 1], aH, bL + 2);
                mma_bf16(sacc[2 * np],     aL, bH);
                mma_bf16(sacc[2 * np + 1], aL, bH + 2);
            }
        }

        #pragma unroll
        for (int nb = 0; nb < 4; nb++) {
            int col = 32 * wc + 8 * nb + 2 * lt;
            int r0  = 16 * wr + lg;
            Sm[r0 * 65 + col]     = (s0 + col     <= q0 + r0) ? sacc[nb][0] : -3.0e38f;
            Sm[r0 * 65 + col + 1] = (s0 + col + 1 <= q0 + r0) ? sacc[nb][1] : -3.0e38f;
            int r1 = r0 + 8;
            Sm[r1 * 65 + col]     = (s0 + col     <= q0 + r1) ? sacc[nb][2] : -3.0e38f;
            Sm[r1 * 65 + col + 1] = (s0 + col + 1 <= q0 + r1) ? sacc[nb][3] : -3.0e38f;
        }
        __syncthreads();

        load_tile64(smp, OFF_KH, vh + (size_t)s0 * NH, t);
        load_tile64(smp, OFF_KL, vl + (size_t)s0 * NH, t);

        {
            float pm = -3.0e38f;
            #pragma unroll
            for (int c = q4 * 16; c < q4 * 16 + 16; c++)
                pm = fmaxf(pm, Sm[rr * 65 + c]);
            red[q4 * 64 + rr] = pm;
        }
        __syncthreads();
        if (t < 64) {
            float m_old = mrow[t];
            float m_new = fmaxf(m_old,
                          fmaxf(fmaxf(red[t], red[64 + t]),
                                fmaxf(red[128 + t], red[192 + t])));
            float al = __expf(m_old - m_new);
            mrow[t] = m_new; arow[t] = al; lrow[t] *= al;
        }
        __syncthreads();

        {
            float mn = mrow[rr];
            float ps = 0.f;
            __nv_bfloat16* Ph = (__nv_bfloat16*)(smp + OFF_PHI) + rr * PSTR;
            __nv_bfloat16* Pl = (__nv_bfloat16*)(smp + OFF_PLO) + rr * PSTR;
            #pragma unroll
            for (int c = q4 * 16; c < q4 * 16 + 16; c++) {
                float p = __expf(Sm[rr * 65 + c] - mn);
                ps += p;
                __nv_bfloat16 h = __float2bfloat16(p);
                Ph[c] = h;
                Pl[c] = __float2bfloat16(p - __bfloat162float(h));
            }
            red[q4 * 64 + rr] = ps;
        }
        __syncthreads();
        if (t < 64)
            lrow[t] += red[t] + red[64 + t] + red[128 + t] + red[192 + t];

        {
            float a0 = arow[16 * wr + lg];
            float a1 = arow[16 * wr + 8 + lg];
            #pragma unroll
            for (int nb = 0; nb < 16; nb++) {
                oacc[nb][0] *= a0; oacc[nb][1] *= a0;
                oacc[nb][2] *= a1; oacc[nb][3] *= a1;
            }
        }
        __syncthreads();

        #pragma unroll
        for (int ks = 0; ks < 4; ks++) {
            const int s = 16 * ks;
            uint32_t aH[4], aL[4];
            uint32_t pa = sb + OFF_PHI + (16 * wr + (l & 15)) * PROW_B
                        + (s + ((l >> 4) << 3)) * 2;
            ldmx4(aH, pa);
            ldmx4(aL, pa + (OFF_PLO - OFF_PHI));
            #pragma unroll
            for (int nb = 0; nb < 8; nb++) {
                const int h0 = 128 * wc + 16 * nb;
                uint32_t va = sb + OFF_KH
                            + (s + (l & 7) + (((l >> 3) & 1) << 3)) * QROW_B
                            + (h0 + ((l >> 4) << 3)) * 2;
                uint32_t bH[4], bL[4];
                ldmx4t(bH, va);
                ldmx4t(bL, va + (OFF_KL - OFF_KH));
                mma_bf16(oacc[2 * nb],     aH, bH);
                mma_bf16(oacc[2 * nb + 1], aH, bH + 2);
                mma_bf16(oacc[2 * nb],     aH, bL);
                mma_bf16(oacc[2 * nb + 1], aH, bL + 2);
                mma_bf16(oacc[2 * nb],     aL, bH);
                mma_bf16(oacc[2 * nb + 1], aL, bH + 2);
            }
        }
    }

    __syncthreads();
    {
        int g0 = 16 * wr + lg;
        int g1 = g0 + 8;
        float inv0 = 1.0f / lrow[g0];
        float inv1 = 1.0f / lrow[g1];
        float* o0 = out + ((size_t)b * NT + q0 + g0) * NH;
        float* o1 = out + ((size_t)b * NT + q0 + g1) * NH;
        #pragma unroll
        for (int nb = 0; nb < 16; nb++) {
            int col = 128 * wc + 8 * nb + 2 * lt;
            *(float2*)&o0[col] = make_float2(oacc[nb][0] * inv0, oacc[nb][1] * inv0);
            *(float2*)&o1[col] = make_float2(oacc[nb][2] * inv1, oacc[nb][3] * inv1);
        }
    }
}

// ---------------------------------------------------------------------------
extern "C" void kernel_launch(void* const* d_in, const int* in_sizes, int n_in,
                              void* d_out, int out_size)
{
    const float* x  = (const float*)d_in[0];
    const float* Wq = (const float*)d_in[1];
    const float* Wk = (const float*)d_in[2];
    const float* Wv = (const float*)d_in[3];
    float* out = (float*)d_out;

    cudaFuncSetAttribute(attn_mma_kernel,
                         cudaFuncAttributeMaxDynamicSharedMemorySize, ATTN_SMEM);

    qkv_gemm_kernel<<<dim3(2, (NB * NT) / 128, 3), 256>>>(x, Wq, Wk, Wv);
    attn_mma_kernel<<<dim3(NT / 64, NB), 256, ATTN_SMEM>>>(out);
}

// round 7
// speedup vs baseline: 3.7215x; 1.1233x over previous
#include <cuda_runtime.h>
#include <cuda_bf16.h>
#include <cstdint>

// Problem constants
#define NB 8
#define NT 2048
#define NC 1024
#define NH 256

// Scratch (device globals)
__device__ __nv_bfloat16 g_qhi[NB*NT*NH], g_qlo[NB*NT*NH];
__device__ __nv_bfloat16 g_khi[NB*NT*NH], g_klo[NB*NT*NH];
__device__ __nv_bfloat16 g_vhi[NB*NT*NH], g_vlo[NB*NT*NH];
__device__ __nv_bfloat16 g_xhi[NB*NT*NC], g_xlo[NB*NT*NC];
__device__ __nv_bfloat16 g_whi[3*NC*NH],  g_wlo[3*NC*NH];

__device__ __forceinline__ uint32_t smem_u32(const void* p) {
    uint32_t a;
    asm("{ .reg .u64 t; cvta.to.shared.u64 t, %1; cvt.u32.u64 %0, t; }"
        : "=r"(a) : "l"(p));
    return a;
}
__device__ __forceinline__ void ldmx4(uint32_t* r, uint32_t addr) {
    asm volatile("ldmatrix.sync.aligned.m8n8.x4.shared.b16 {%0,%1,%2,%3}, [%4];"
        : "=r"(r[0]), "=r"(r[1]), "=r"(r[2]), "=r"(r[3]) : "r"(addr));
}
__device__ __forceinline__ void ldmx4t(uint32_t* r, uint32_t addr) {
    asm volatile("ldmatrix.sync.aligned.m8n8.x4.trans.shared.b16 {%0,%1,%2,%3}, [%4];"
        : "=r"(r[0]), "=r"(r[1]), "=r"(r[2]), "=r"(r[3]) : "r"(addr));
}
__device__ __forceinline__ void mma_bf16(float* c, const uint32_t* a, const uint32_t* b) {
    asm volatile("mma.sync.aligned.m16n8k16.row.col.f32.bf16.bf16.f32 "
        "{%0,%1,%2,%3}, {%4,%5,%6,%7}, {%8,%9}, {%0,%1,%2,%3};"
        : "+f"(c[0]), "+f"(c[1]), "+f"(c[2]), "+f"(c[3])
        : "r"(a[0]), "r"(a[1]), "r"(a[2]), "r"(a[3]), "r"(b[0]), "r"(b[1]));
}
__device__ __forceinline__ void cpa16(uint32_t dst, const void* src) {
    asm volatile("cp.async.cg.shared.global [%0], [%1], 16;" :: "r"(dst), "l"(src));
}
#define CP_COMMIT() asm volatile("cp.async.commit_group;" ::: "memory")
#define CP_WAIT1()  asm volatile("cp.async.wait_group 1;" ::: "memory")
#define CP_WAIT0()  asm volatile("cp.async.wait_group 0;" ::: "memory")

__device__ __forceinline__ uint32_t packbb(__nv_bfloat16 a, __nv_bfloat16 b) {
    unsigned short ua = *reinterpret_cast<unsigned short*>(&a);
    unsigned short ub = *reinterpret_cast<unsigned short*>(&b);
    return (uint32_t)ua | ((uint32_t)ub << 16);
}
__device__ __forceinline__ void split2(float v0, float v1, uint32_t& hw, uint32_t& lw) {
    __nv_bfloat16 h0 = __float2bfloat16(v0);
    __nv_bfloat16 h1 = __float2bfloat16(v1);
    __nv_bfloat16 l0 = __float2bfloat16(v0 - __bfloat162float(h0));
    __nv_bfloat16 l1 = __float2bfloat16(v1 - __bfloat162float(h1));
    hw = packbb(h0, h1);
    lw = packbb(l0, l1);
}

// ---------------------------------------------------------------------------
// Prep kernels: fp32 -> split bf16 hi/lo
// ---------------------------------------------------------------------------
__global__ void __launch_bounds__(256)
convert_x_kernel(const float* __restrict__ x)
{
    int idx = blockIdx.x * 256 + threadIdx.x;    // float4 index, 4M total
    float4 v = ((const float4*)x)[idx];
    uint32_t h01, l01, h23, l23;
    split2(v.x, v.y, h01, l01);
    split2(v.z, v.w, h23, l23);
    ((uint2*)g_xhi)[idx] = make_uint2(h01, h23);
    ((uint2*)g_xlo)[idx] = make_uint2(l01, l23);
}

__global__ void __launch_bounds__(256)
convert_w_kernel(const float* __restrict__ Wq, const float* __restrict__ Wk,
                 const float* __restrict__ Wv)
{
    int idx = blockIdx.x * 256 + threadIdx.x;    // float4 index, 196608 total
    int z = idx >> 16;                            // 65536 float4 per matrix
    int j = idx & 65535;
    const float* W = (z == 0) ? Wq : ((z == 1) ? Wk : Wv);
    float s = (z == 0) ? 16.0f : 1.0f;           // fold sqrt(H) into Wq
    float4 v = ((const float4*)W)[j];
    uint32_t h01, l01, h23, l23;
    split2(v.x * s, v.y * s, h01, l01);
    split2(v.z * s, v.w * s, h23, l23);
    ((uint2*)g_whi)[idx] = make_uint2(h01, h23);
    ((uint2*)g_wlo)[idx] = make_uint2(l01, l23);
}

// ---------------------------------------------------------------------------
// Kernel 1: QKV projection GEMM, split-bf16 mma.sync, cp.async double buffer.
// CTA 128x128, BK=32, 256 threads, warp grid 2(m)x4(n).
// ---------------------------------------------------------------------------
#define ASTR 40
#define WSTR 136
#define G_AH  0
#define G_AL  10240
#define G_WH  20480
#define G_WL  29184
#define G_BUF 37888
#define GEMM_SMEM (2 * G_BUF)

__device__ __forceinline__ void gemm_issue(uint32_t sbuf, const __nv_bfloat16* xh,
                                           const __nv_bfloat16* xl,
                                           const __nv_bfloat16* wh,
                                           const __nv_bfloat16* wl,
                                           int m0, int n0, int k0, int t)
{
    #pragma unroll
    for (int i = 0; i < 2; i++) {
        int idx = t + 256 * i;
        {   // A: 128 rows x 4 segs (32 cols)
            int row = idx >> 2, seg = idx & 3;
            uint32_t d = sbuf + G_AH + row * (ASTR * 2) + seg * 16;
            size_t   g = (size_t)(m0 + row) * NC + k0 + seg * 8;
            cpa16(d, xh + g);
            cpa16(d + (G_AL - G_AH), xl + g);
        }
        {   // W: 32 rows x 16 segs (128 cols)
            int row = idx >> 4, seg = idx & 15;
            uint32_t d = sbuf + G_WH + row * (WSTR * 2) + seg * 16;
            size_t   g = (size_t)(k0 + row) * NH + n0 + seg * 8;
            cpa16(d, wh + g);
            cpa16(d + (G_WL - G_WH), wl + g);
        }
    }
}

__global__ void __launch_bounds__(256, 1)
qkv_gemm_kernel()
{
    extern __shared__ char smg[];
    const uint32_t sb = smem_u32(smg);

    const int z = blockIdx.z;
    const __nv_bfloat16* wh = g_whi + (size_t)z * NC * NH;
    const __nv_bfloat16* wl = g_wlo + (size_t)z * NC * NH;
    __nv_bfloat16* ohi = (z == 0) ? g_qhi : ((z == 1) ? g_khi : g_vhi);
    __nv_bfloat16* olo = (z == 0) ? g_qlo : ((z == 1) ? g_klo : g_vlo);

    const int m0 = blockIdx.y * 128;
    const int n0 = blockIdx.x * 128;
    const int t  = threadIdx.x;
    const int l  = t & 31;
    const int wid = t >> 5;
    const int wm = wid & 1;
    const int wn = wid >> 1;
    const int lg = l >> 2;
    const int lt = l & 3;

    float acc[4][4][4];
    #pragma unroll
    for (int i = 0; i < 4; i++)
        #pragma unroll
        for (int j = 0; j < 4; j++)
            #pragma unroll
            for (int k = 0; k < 4; k++) acc[i][j][k] = 0.f;

    // prologue: tile 0 into buf 0
    gemm_issue(sb, g_xhi, g_xlo, wh, wl, m0, n0, 0, t);
    CP_COMMIT();

    for (int it = 0; it < 32; it++) {
        if (it + 1 < 32) {
            gemm_issue(sb + ((it + 1) & 1) * G_BUF, g_xhi, g_xlo, wh, wl,
                       m0, n0, (it + 1) * 32, t);
            CP_COMMIT();
            CP_WAIT1();
        } else {
            CP_WAIT0();
        }
        __syncthreads();

        const uint32_t B = sb + (it & 1) * G_BUF;
        #pragma unroll
        for (int ks = 0; ks < 2; ks++) {
            const int k = 16 * ks;
            uint32_t aH[4][4], aL[4][4];
            #pragma unroll
            for (int mi = 0; mi < 4; mi++) {
                uint32_t aa = B + G_AH + ((64 * wm + 16 * mi + (l & 15)) * ASTR
                            + k + ((l >> 4) << 3)) * 2;
                ldmx4(aH[mi], aa);
                ldmx4(aL[mi], aa + (G_AL - G_AH));
            }
            #pragma unroll
            for (int nj = 0; nj < 2; nj++) {
                uint32_t wa = B + G_WH + ((k + (l & 7) + (((l >> 3) & 1) << 3)) * WSTR
                            + 32 * wn + 16 * nj + ((l >> 4) << 3)) * 2;
                uint32_t bH[4], bL[4];
                ldmx4t(bH, wa);
                ldmx4t(bL, wa + (G_WL - G_WH));
                #pragma unroll
                for (int mi = 0; mi < 4; mi++) {
                    mma_bf16(acc[mi][2 * nj],     aH[mi], bH);
                    mma_bf16(acc[mi][2 * nj + 1], aH[mi], bH + 2);
                    mma_bf16(acc[mi][2 * nj],     aH[mi], bL);
                    mma_bf16(acc[mi][2 * nj + 1], aH[mi], bL + 2);
                    mma_bf16(acc[mi][2 * nj],     aL[mi], bH);
                    mma_bf16(acc[mi][2 * nj + 1], aL[mi], bH + 2);
                }
            }
        }
        __syncthreads();
    }

    #pragma unroll
    for (int mi = 0; mi < 4; mi++) {
        #pragma unroll
        for (int ni = 0; ni < 4; ni++) {
            int col = n0 + 32 * wn + 8 * ni + 2 * lt;
            size_t r0 = (size_t)(m0 + 64 * wm + 16 * mi + lg) * NH + col;
            size_t r1 = r0 + 8 * NH;
            uint32_t hw, lw;
            split2(acc[mi][ni][0], acc[mi][ni][1], hw, lw);
            *(uint32_t*)&ohi[r0] = hw;
            *(uint32_t*)&olo[r0] = lw;
            split2(acc[mi][ni][2], acc[mi][ni][3], hw, lw);
            *(uint32_t*)&ohi[r1] = hw;
            *(uint32_t*)&olo[r1] = lw;
        }
    }
}

// ---------------------------------------------------------------------------
// Kernel 2: flash attention, register softmax (FA2-style), cp.async pipeline.
// 128 threads = 4 warps; warp w owns rows 16w..16w+15 x full width.
// TQ=64, TS=32. KV tiles (K hi/lo + V hi/lo) double-buffered.
// ---------------------------------------------------------------------------
#define QSTR 264
#define QROW_B (QSTR * 2)        // 528
#define TSA 32

#define A_QHI 0
#define A_QLO (64 * QROW_B)                  // 33792
#define A_BUF0 (2 * 64 * QROW_B)             // 67584
#define T_KH 0
#define T_KL (TSA * QROW_B)                  // 16896
#define T_VH (2 * TSA * QROW_B)              // 33792
#define T_VL (3 * TSA * QROW_B)              // 50688
#define A_BUFSZ (4 * TSA * QROW_B)           // 67584
#define ATTN_SMEM (A_BUF0 + 2 * A_BUFSZ)     // 202752

__device__ __forceinline__ void attn_issue(uint32_t sbuf,
    const __nv_bfloat16* kh, const __nv_bfloat16* kl,
    const __nv_bfloat16* vh, const __nv_bfloat16* vl, int s0, int t)
{
    #pragma unroll
    for (int i = 0; i < 8; i++) {
        int idx = t + i * 128;
        int row = idx >> 5, seg = idx & 31;    // 32 rows x 32 segs
        uint32_t d = sbuf + row * QROW_B + seg * 16;
        size_t   g = (size_t)(s0 + row) * NH + seg * 8;
        cpa16(d + T_KH, kh + g);
        cpa16(d + T_KL, kl + g);
        cpa16(d + T_VH, vh + g);
        cpa16(d + T_VL, vl + g);
    }
}

__global__ void __launch_bounds__(128, 1)
attn_mma_kernel(float* __restrict__ out)
{
    extern __shared__ char smp[];
    const uint32_t sb = smem_u32(smp);

    const int t   = threadIdx.x;
    const int wid = t >> 5;
    const int l   = t & 31;
    const int lg  = l >> 2;
    const int lt  = l & 3;
    const int b   = blockIdx.y;
    const int q0  = blockIdx.x * 64;

    // Q tile (hi+lo) -> smem, plain loads
    {
        const __nv_bfloat16* qh = g_qhi + ((size_t)b * NT + q0) * NH;
        const __nv_bfloat16* ql = g_qlo + ((size_t)b * NT + q0) * NH;
        #pragma unroll
        for (int i = 0; i < 16; i++) {
            int idx = t + i * 128;
            int row = idx >> 5, seg = idx & 31;   // 64 rows x 32 segs
            size_t g = (size_t)row * NH + seg * 8;
            *(uint4*)(smp + A_QHI + row * QROW_B + seg * 16) = *(const uint4*)(qh + g);
            *(uint4*)(smp + A_QLO + row * QROW_B + seg * 16) = *(const uint4*)(ql + g);
        }
    }

    const __nv_bfloat16* kh = g_khi + (size_t)b * NT * NH;
    const __nv_bfloat16* kl = g_klo + (size_t)b * NT * NH;
    const __nv_bfloat16* vh = g_vhi + (size_t)b * NT * NH;
    const __nv_bfloat16* vl = g_vlo + (size_t)b * NT * NH;

    float oacc[32][4];
    #pragma unroll
    for (int i = 0; i < 32; i++)
        #pragma unroll
        for (int j = 0; j < 4; j++) oacc[i][j] = 0.f;

    float m0v = -3.0e38f, m1v = -3.0e38f, l0v = 0.f, l1v = 0.f;
    const int r0g = q0 + 16 * wid + lg;       // this thread's two rows
    const int r1g = r0g + 8;
    const int wrow_lo = q0 + 16 * wid;        // lowest row of warp
    const int wrow_hi = wrow_lo + 15;

    const int ntiles = q0 / TSA + 2;

    attn_issue(sb + A_BUF0, kh, kl, vh, vl, 0, t);
    CP_COMMIT();

    for (int it = 0; it < ntiles; it++) {
        const int s0 = it * TSA;
        if (it + 1 < ntiles) {
            attn_issue(sb + A_BUF0 + ((it + 1) & 1) * A_BUFSZ, kh, kl, vh, vl,
                       (it + 1) * TSA, t);
            CP_COMMIT();
            CP_WAIT1();
        } else {
            CP_WAIT0();
        }
        __syncthreads();

        if (s0 <= wrow_hi) {                  // warp-uniform skip
            const uint32_t B = sb + A_BUF0 + (it & 1) * A_BUFSZ;

            // ---- S = Qhi*Khi + Qhi*Klo + Qlo*Khi (warp tile 16 x 32)
            float sacc[4][4];
            #pragma unroll
            for (int i = 0; i < 4; i++)
                #pragma unroll
                for (int j = 0; j < 4; j++) sacc[i][j] = 0.f;

            #pragma unroll 4
            for (int kk = 0; kk < 16; kk++) {
                const int k = kk * 16;
                uint32_t aH[4], aL[4];
                uint32_t qa = sb + A_QHI + (16 * wid + (l & 15)) * QROW_B
                            + (k + ((l >> 4) << 3)) * 2;
                ldmx4(aH, qa);
                ldmx4(aL, qa + (A_QLO - A_QHI));
                #pragma unroll
                for (int np = 0; np < 2; np++) {
                    uint32_t ka = B + T_KH
                                + (16 * np + (l & 7) + ((l >> 4) << 3)) * QROW_B
                                + (k + (((l >> 3) & 1) << 3)) * 2;
                    uint32_t bH[4], bL[4];
                    ldmx4(bH, ka);
                    ldmx4(bL, ka + (T_KL - T_KH));
                    mma_bf16(sacc[2 * np],     aH, bH);
                    mma_bf16(sacc[2 * np + 1], aH, bH + 2);
                    mma_bf16(sacc[2 * np],     aH, bL);
                    mma_bf16(sacc[2 * np + 1], aH, bL + 2);
                    mma_bf16(sacc[2 * np],     aL, bH);
                    mma_bf16(sacc[2 * np + 1], aL, bH + 2);
                }
            }

            // ---- causal mask (register)
            #pragma unroll
            for (int nb = 0; nb < 4; nb++) {
                int c = s0 + 8 * nb + 2 * lt;
                if (c     > r0g) sacc[nb][0] = -3.0e38f;
                if (c + 1 > r0g) sacc[nb][1] = -3.0e38f;
                if (c     > r1g) sacc[nb][2] = -3.0e38f;
                if (c + 1 > r1g) sacc[nb][3] = -3.0e38f;
            }

            // ---- row max via quad shuffle
            float mx0 = -3.0e38f, mx1 = -3.0e38f;
            #pragma unroll
            for (int nb = 0; nb < 4; nb++) {
                mx0 = fmaxf(mx0, fmaxf(sacc[nb][0], sacc[nb][1]));
                mx1 = fmaxf(mx1, fmaxf(sacc[nb][2], sacc[nb][3]));
            }
            mx0 = fmaxf(mx0, __shfl_xor_sync(0xffffffff, mx0, 1));
            mx0 = fmaxf(mx0, __shfl_xor_sync(0xffffffff, mx0, 2));
            mx1 = fmaxf(mx1, __shfl_xor_sync(0xffffffff, mx1, 1));
            mx1 = fmaxf(mx1, __shfl_xor_sync(0xffffffff, mx1, 2));

            float mn0 = fmaxf(m0v, mx0);
            float mn1 = fmaxf(m1v, mx1);
            float al0 = __expf(m0v - mn0);
            float al1 = __expf(m1v - mn1);
            m0v = mn0; m1v = mn1;

            // ---- P = exp(S - m) -> direct A-fragments (hi/lo)
            uint32_t pfh[2][4], pfl[2][4];
            float ps0 = 0.f, ps1 = 0.f;
            #pragma unroll
            for (int nb = 0; nb < 4; nb++) {
                float e0 = __expf(sacc[nb][0] - mn0);
                float e1 = __expf(sacc[nb][1] - mn0);
                float e2 = __expf(sacc[nb][2] - mn1);
                float e3 = __expf(sacc[nb][3] - mn1);
                ps0 += e0 + e1;
                ps1 += e2 + e3;
                int ks = nb >> 1, jj = (nb & 1) << 1;
                uint32_t hw, lw;
                split2(e0, e1, hw, lw);
                pfh[ks][jj] = hw; pfl[ks][jj] = lw;
                split2(e2, e3, hw, lw);
                pfh[ks][jj + 1] = hw; pfl[ks][jj + 1] = lw;
            }
            ps0 += __shfl_xor_sync(0xffffffff, ps0, 1);
            ps0 += __shfl_xor_sync(0xffffffff, ps0, 2);
            ps1 += __shfl_xor_sync(0xffffffff, ps1, 1);
            ps1 += __shfl_xor_sync(0xffffffff, ps1, 2);
            l0v = l0v * al0 + ps0;
            l1v = l1v * al1 + ps1;

            // ---- O rescale
            #pragma unroll
            for (int nb = 0; nb < 32; nb++) {
                oacc[nb][0] *= al0; oacc[nb][1] *= al0;
                oacc[nb][2] *= al1; oacc[nb][3] *= al1;
            }

            // ---- PV: O += Phi*Vhi + Phi*Vlo + Plo*Vhi
            #pragma unroll
            for (int ks = 0; ks < 2; ks++) {
                #pragma unroll
                for (int hb = 0; hb < 16; hb++) {
                    uint32_t va = B + T_VH
                                + (16 * ks + (l & 7) + (((l >> 3) & 1) << 3)) * QROW_B
                                + (16 * hb + ((l >> 4) << 3)) * 2;
                    uint32_t bH[4], bL[4];
                    ldmx4t(bH, va);
                    ldmx4t(bL, va + (T_VL - T_VH));
                    mma_bf16(oacc[2 * hb],     pfh[ks], bH);
                    mma_bf16(oacc[2 * hb + 1], pfh[ks], bH + 2);
                    mma_bf16(oacc[2 * hb],     pfh[ks], bL);
                    mma_bf16(oacc[2 * hb + 1], pfh[ks], bL + 2);
                    mma_bf16(oacc[2 * hb],     pfl[ks], bH);
                    mma_bf16(oacc[2 * hb + 1], pfl[ks], bH + 2);
                }
            }
        }
        __syncthreads();
    }

    // ---- epilogue: out = O / l
    {
        float inv0 = 1.0f / l0v;
        float inv1 = 1.0f / l1v;
        float* o0 = out + ((size_t)b * NT + r0g) * NH;
        float* o1 = out + ((size_t)b * NT + r1g) * NH;
        #pragma unroll
        for (int nb = 0; nb < 32; nb++) {
            int col = 8 * nb + 2 * lt;
            *(float2*)&o0[col] = make_float2(oacc[nb][0] * inv0, oacc[nb][1] * inv0);
            *(float2*)&o1[col] = make_float2(oacc[nb][2] * inv1, oacc[nb][3] * inv1);
        }
    }
}

// ---------------------------------------------------------------------------
extern "C" void kernel_launch(void* const* d_in, const int* in_sizes, int n_in,
                              void* d_out, int out_size)
{
    const float* x  = (const float*)d_in[0];
    const float* Wq = (const float*)d_in[1];
    const float* Wk = (const float*)d_in[2];
    const float* Wv = (const float*)d_in[3];
    float* out = (float*)d_out;

    cudaFuncSetAttribute(qkv_gemm_kernel,
                         cudaFuncAttributeMaxDynamicSharedMemorySize, GEMM_SMEM);
    cudaFuncSetAttribute(attn_mma_kernel,
                         cudaFuncAttributeMaxDynamicSharedMemorySize, ATTN_SMEM);

    convert_x_kernel<<<16384, 256>>>(x);
    convert_w_kernel<<<768, 256>>>(Wq, Wk, Wv);
    qkv_gemm_kernel<<<dim3(2, (NB * NT) / 128, 3), 256, GEMM_SMEM>>>();
    attn_mma_kernel<<<dim3(NT / 64, NB), 128, ATTN_SMEM>>>(out);
}

// round 10
// speedup vs baseline: 3.9840x; 1.0705x over previous
#include <cuda_runtime.h>
#include <cuda_bf16.h>
#include <cstdint>

// Problem constants
#define NB 8
#define NT 2048
#define NC 1024
#define NH 256

// Scratch (device globals)
__device__ __nv_bfloat16 g_qhi[NB*NT*NH], g_qlo[NB*NT*NH];
__device__ __nv_bfloat16 g_khi[NB*NT*NH], g_klo[NB*NT*NH];
__device__ __nv_bfloat16 g_vhi[NB*NT*NH], g_vlo[NB*NT*NH];
__device__ __nv_bfloat16 g_xhi[NB*NT*NC], g_xlo[NB*NT*NC];
__device__ __nv_bfloat16 g_whi[3*NC*NH],  g_wlo[3*NC*NH];

__device__ __forceinline__ uint32_t smem_u32(const void* p) {
    uint32_t a;
    asm("{ .reg .u64 t; cvta.to.shared.u64 t, %1; cvt.u32.u64 %0, t; }"
        : "=r"(a) : "l"(p));
    return a;
}
__device__ __forceinline__ void ldmx4(uint32_t* r, uint32_t addr) {
    asm volatile("ldmatrix.sync.aligned.m8n8.x4.shared.b16 {%0,%1,%2,%3}, [%4];"
        : "=r"(r[0]), "=r"(r[1]), "=r"(r[2]), "=r"(r[3]) : "r"(addr));
}
__device__ __forceinline__ void ldmx4t(uint32_t* r, uint32_t addr) {
    asm volatile("ldmatrix.sync.aligned.m8n8.x4.trans.shared.b16 {%0,%1,%2,%3}, [%4];"
        : "=r"(r[0]), "=r"(r[1]), "=r"(r[2]), "=r"(r[3]) : "r"(addr));
}
__device__ __forceinline__ void mma_bf16(float* c, const uint32_t* a, const uint32_t* b) {
    asm volatile("mma.sync.aligned.m16n8k16.row.col.f32.bf16.bf16.f32 "
        "{%0,%1,%2,%3}, {%4,%5,%6,%7}, {%8,%9}, {%0,%1,%2,%3};"
        : "+f"(c[0]), "+f"(c[1]), "+f"(c[2]), "+f"(c[3])
        : "r"(a[0]), "r"(a[1]), "r"(a[2]), "r"(a[3]), "r"(b[0]), "r"(b[1]));
}
__device__ __forceinline__ void cpa16(uint32_t dst, const void* src) {
    asm volatile("cp.async.cg.shared.global [%0], [%1], 16;" :: "r"(dst), "l"(src));
}
#define CP_COMMIT() asm volatile("cp.async.commit_group;" ::: "memory")
#define CP_WAIT1()  asm volatile("cp.async.wait_group 1;" ::: "memory")
#define CP_WAIT0()  asm volatile("cp.async.wait_group 0;" ::: "memory")

__device__ __forceinline__ uint32_t packbb(__nv_bfloat16 a, __nv_bfloat16 b) {
    unsigned short ua = *reinterpret_cast<unsigned short*>(&a);
    unsigned short ub = *reinterpret_cast<unsigned short*>(&b);
    return (uint32_t)ua | ((uint32_t)ub << 16);
}
__device__ __forceinline__ void split2(float v0, float v1, uint32_t& hw, uint32_t& lw) {
    __nv_bfloat16 h0 = __float2bfloat16(v0);
    __nv_bfloat16 h1 = __float2bfloat16(v1);
    __nv_bfloat16 l0 = __float2bfloat16(v0 - __bfloat162float(h0));
    __nv_bfloat16 l1 = __float2bfloat16(v1 - __bfloat162float(h1));
    hw = packbb(h0, h1);
    lw = packbb(l0, l1);
}

// ---------------------------------------------------------------------------
// Prep kernels: fp32 -> split bf16 hi/lo
// ---------------------------------------------------------------------------
__global__ void __launch_bounds__(256)
convert_x_kernel(const float* __restrict__ x)
{
    int idx = blockIdx.x * 256 + threadIdx.x;
    float4 v = ((const float4*)x)[idx];
    uint32_t h01, l01, h23, l23;
    split2(v.x, v.y, h01, l01);
    split2(v.z, v.w, h23, l23);
    ((uint2*)g_xhi)[idx] = make_uint2(h01, h23);
    ((uint2*)g_xlo)[idx] = make_uint2(l01, l23);
}

__global__ void __launch_bounds__(256)
convert_w_kernel(const float* __restrict__ Wq, const float* __restrict__ Wk,
                 const float* __restrict__ Wv)
{
    int idx = blockIdx.x * 256 + threadIdx.x;
    int z = idx >> 16;
    int j = idx & 65535;
    const float* W = (z == 0) ? Wq : ((z == 1) ? Wk : Wv);
    float s = (z == 0) ? 16.0f : 1.0f;           // fold sqrt(H) into Wq
    float4 v = ((const float4*)W)[j];
    uint32_t h01, l01, h23, l23;
    split2(v.x * s, v.y * s, h01, l01);
    split2(v.z * s, v.w * s, h23, l23);
    ((uint2*)g_whi)[idx] = make_uint2(h01, h23);
    ((uint2*)g_wlo)[idx] = make_uint2(l01, l23);
}

// ---------------------------------------------------------------------------
// Kernel 1: QKV projection GEMM, split-bf16 mma.sync, cp.async double buffer.
// CTA 128x128, BK=32, 256 threads, warp grid 2(m)x4(n). Target 2 CTAs/SM.
// ---------------------------------------------------------------------------
#define ASTR 40
#define WSTR 136
#define G_AH  0
#define G_AL  10240
#define G_WH  20480
#define G_WL  29184
#define G_BUF 37888
#define GEMM_SMEM (2 * G_BUF)

__device__ __forceinline__ void gemm_issue(uint32_t sbuf, const __nv_bfloat16* xh,
                                           const __nv_bfloat16* xl,
                                           const __nv_bfloat16* wh,
                                           const __nv_bfloat16* wl,
                                           int m0, int n0, int k0, int t)
{
    #pragma unroll
    for (int i = 0; i < 2; i++) {
        int idx = t + 256 * i;
        {
            int row = idx >> 2, seg = idx & 3;
            uint32_t d = sbuf + G_AH + row * (ASTR * 2) + seg * 16;
            size_t   g = (size_t)(m0 + row) * NC + k0 + seg * 8;
            cpa16(d, xh + g);
            cpa16(d + (G_AL - G_AH), xl + g);
        }
        {
            int row = idx >> 4, seg = idx & 15;
            uint32_t d = sbuf + G_WH + row * (WSTR * 2) + seg * 16;
            size_t   g = (size_t)(k0 + row) * NH + n0 + seg * 8;
            cpa16(d, wh + g);
            cpa16(d + (G_WL - G_WH), wl + g);
        }
    }
}

__global__ void __launch_bounds__(256, 2)
qkv_gemm_kernel()
{
    extern __shared__ char smg[];
    const uint32_t sb = smem_u32(smg);

    const int z = blockIdx.z;
    const __nv_bfloat16* wh = g_whi + (size_t)z * NC * NH;
    const __nv_bfloat16* wl = g_wlo + (size_t)z * NC * NH;
    __nv_bfloat16* ohi = (z == 0) ? g_qhi : ((z == 1) ? g_khi : g_vhi);
    __nv_bfloat16* olo = (z == 0) ? g_qlo : ((z == 1) ? g_klo : g_vlo);

    const int m0 = blockIdx.y * 128;
    const int n0 = blockIdx.x * 128;
    const int t  = threadIdx.x;
    const int l  = t & 31;
    const int wid = t >> 5;
    const int wm = wid & 1;
    const int wn = wid >> 1;
    const int lg = l >> 2;
    const int lt = l & 3;

    float acc[4][4][4];
    #pragma unroll
    for (int i = 0; i < 4; i++)
        #pragma unroll
        for (int j = 0; j < 4; j++)
            #pragma unroll
            for (int k = 0; k < 4; k++) acc[i][j][k] = 0.f;

    gemm_issue(sb, g_xhi, g_xlo, wh, wl, m0, n0, 0, t);
    CP_COMMIT();

    for (int it = 0; it < 32; it++) {
        if (it + 1 < 32) {
            gemm_issue(sb + ((it + 1) & 1) * G_BUF, g_xhi, g_xlo, wh, wl,
                       m0, n0, (it + 1) * 32, t);
            CP_COMMIT();
            CP_WAIT1();
        } else {
            CP_WAIT0();
        }
        __syncthreads();

        const uint32_t B = sb + (it & 1) * G_BUF;
        #pragma unroll
        for (int ks = 0; ks < 2; ks++) {
            const int k = 16 * ks;
            uint32_t aH[4][4], aL[4][4];
            #pragma unroll
            for (int mi = 0; mi < 4; mi++) {
                uint32_t aa = B + G_AH + ((64 * wm + 16 * mi + (l & 15)) * ASTR
                            + k + ((l >> 4) << 3)) * 2;
                ldmx4(aH[mi], aa);
                ldmx4(aL[mi], aa + (G_AL - G_AH));
            }
            #pragma unroll
            for (int nj = 0; nj < 2; nj++) {
                uint32_t wa = B + G_WH + ((k + (l & 7) + (((l >> 3) & 1) << 3)) * WSTR
                            + 32 * wn + 16 * nj + ((l >> 4) << 3)) * 2;
                uint32_t bH[4], bL[4];
                ldmx4t(bH, wa);
                ldmx4t(bL, wa + (G_WL - G_WH));
                #pragma unroll
                for (int mi = 0; mi < 4; mi++) {
                    mma_bf16(acc[mi][2 * nj],     aH[mi], bH);
                    mma_bf16(acc[mi][2 * nj + 1], aH[mi], bH + 2);
                    mma_bf16(acc[mi][2 * nj],     aH[mi], bL);
                    mma_bf16(acc[mi][2 * nj + 1], aH[mi], bL + 2);
                    mma_bf16(acc[mi][2 * nj],     aL[mi], bH);
                    mma_bf16(acc[mi][2 * nj + 1], aL[mi], bH + 2);
                }
            }
        }
        __syncthreads();
    }

    #pragma unroll
    for (int mi = 0; mi < 4; mi++) {
        #pragma unroll
        for (int ni = 0; ni < 4; ni++) {
            int col = n0 + 32 * wn + 8 * ni + 2 * lt;
            size_t r0 = (size_t)(m0 + 64 * wm + 16 * mi + lg) * NH + col;
            size_t r1 = r0 + 8 * NH;
            uint32_t hw, lw;
            split2(acc[mi][ni][0], acc[mi][ni][1], hw, lw);
            *(uint32_t*)&ohi[r0] = hw;
            *(uint32_t*)&olo[r0] = lw;
            split2(acc[mi][ni][2], acc[mi][ni][3], hw, lw);
            *(uint32_t*)&ohi[r1] = hw;
            *(uint32_t*)&olo[r1] = lw;
        }
    }
}

// ---------------------------------------------------------------------------
// Kernel 2: flash attention, 256 threads = 8 warps, warp grid 4(row)x2(half).
// TQ=64, TS=32. Warp computes S[16 x 16] half and O[16 x 128] half.
// Cross-half max/sum via smem; P exchanged through smem (hi/lo bf16).
// ---------------------------------------------------------------------------
#define QSTR 264
#define QROW_B (QSTR * 2)        // 528
#define TSA 32
#define PSTRB 80                 // P row stride bytes (40 bf16)

#define A_QHI 0
#define A_QLO (64 * QROW_B)                  // 33792
#define A_BUF0 (2 * 64 * QROW_B)             // 67584
#define T_KH 0
#define T_KL (TSA * QROW_B)                  // 16896
#define T_VH (2 * TSA * QROW_B)              // 33792
#define T_VL (3 * TSA * QROW_B)              // 50688
#define A_BUFSZ (4 * TSA * QROW_B)           // 67584
#define A_PHI (A_BUF0 + 2 * A_BUFSZ)         // 202752
#define A_PLO (A_PHI + 64 * PSTRB)           // 207872
#define A_RED (A_PLO + 64 * PSTRB)           // 212992
#define ATTN_SMEM (A_RED + 1024)             // 214016

__device__ __forceinline__ void attn_issue(uint32_t sbuf,
    const __nv_bfloat16* kh, const __nv_bfloat16* kl,
    const __nv_bfloat16* vh, const __nv_bfloat16* vl, int s0, int t)
{
    #pragma unroll
    for (int i = 0; i < 4; i++) {
        int idx = t + i * 256;
        int row = idx >> 5, seg = idx & 31;    // 32 rows x 32 segs
        uint32_t d = sbuf + row * QROW_B + seg * 16;
        size_t   g = (size_t)(s0 + row) * NH + seg * 8;
        cpa16(d + T_KH, kh + g);
        cpa16(d + T_KL, kl + g);
        cpa16(d + T_VH, vh + g);
        cpa16(d + T_VL, vl + g);
    }
}

__global__ void __launch_bounds__(256, 1)
attn_mma_kernel(float* __restrict__ out)
{
    extern __shared__ char smp[];
    const uint32_t sb = smem_u32(smp);
    float* redm = (float*)(smp + A_RED);          // [2][64] row max halves
    float* reds = (float*)(smp + A_RED + 512);    // [2][64] row sum halves

    const int t   = threadIdx.x;
    const int wid = t >> 5;
    const int l   = t & 31;
    const int lg  = l >> 2;
    const int lt  = l & 3;
    const int wr  = wid & 3;          // row group: rows 16wr..16wr+15
    const int wc  = wid >> 2;         // half: S keys 16wc.., O cols 128wc..
    const int b   = blockIdx.y;
    const int q0  = ((NT / 64 - 1) - blockIdx.x) * 64;   // heavy tiles first

    // Q tile (hi+lo) -> smem
    {
        const __nv_bfloat16* qh = g_qhi + ((size_t)b * NT + q0) * NH;
        const __nv_bfloat16* ql = g_qlo + ((size_t)b * NT + q0) * NH;
        #pragma unroll
        for (int i = 0; i < 8; i++) {
            int idx = t + i * 256;
            int row = idx >> 5, seg = idx & 31;
            size_t g = (size_t)row * NH + seg * 8;
            *(uint4*)(smp + A_QHI + row * QROW_B + seg * 16) = *(const uint4*)(qh + g);
            *(uint4*)(smp + A_QLO + row * QROW_B + seg * 16) = *(const uint4*)(ql + g);
        }
    }

    const __nv_bfloat16* kh = g_khi + (size_t)b * NT * NH;
    const __nv_bfloat16* kl = g_klo + (size_t)b * NT * NH;
    const __nv_bfloat16* vh = g_vhi + (size_t)b * NT * NH;
    const __nv_bfloat16* vl = g_vlo + (size_t)b * NT * NH;

    float oacc[16][4];                // O half: 16 rows x 128 cols
    #pragma unroll
    for (int i = 0; i < 16; i++)
        #pragma unroll
        for (int j = 0; j < 4; j++) oacc[i][j] = 0.f;

    float m0v = -3.0e38f, m1v = -3.0e38f, l0v = 0.f, l1v = 0.f;
    const int r0l = 16 * wr + lg;     // local rows
    const int r1l = r0l + 8;
    const int r0g = q0 + r0l;
    const int r1g = q0 + r1l;

    const int ntiles = q0 / TSA + 2;

    attn_issue(sb + A_BUF0, kh, kl, vh, vl, 0, t);
    CP_COMMIT();

    for (int it = 0; it < ntiles; it++) {
        const int s0 = it * TSA;
        CP_WAIT0();
        __syncthreads();                               // sync A: tile visible
        const uint32_t B = sb + A_BUF0 + (it & 1) * A_BUFSZ;

        // ---- S half = Qhi*Khi + Qhi*Klo + Qlo*Khi (16 rows x 16 keys)
        float sacc[2][4];
        #pragma unroll
        for (int i = 0; i < 2; i++)
            #pragma unroll
            for (int j = 0; j < 4; j++) sacc[i][j] = 0.f;

        #pragma unroll 4
        for (int kk = 0; kk < 16; kk++) {
            const int k = kk * 16;
            uint32_t aH[4], aL[4];
            uint32_t qa = sb + A_QHI + (16 * wr + (l & 15)) * QROW_B
                        + (k + ((l >> 4) << 3)) * 2;
            ldmx4(aH, qa);
            ldmx4(aL, qa + (A_QLO - A_QHI));
            uint32_t ka = B + T_KH
                        + (16 * wc + (l & 7) + ((l >> 4) << 3)) * QROW_B
                        + (k + (((l >> 3) & 1) << 3)) * 2;
            uint32_t bH[4], bL[4];
            ldmx4(bH, ka);
            ldmx4(bL, ka + (T_KL - T_KH));
            mma_bf16(sacc[0], aH, bH);
            mma_bf16(sacc[1], aH, bH + 2);
            mma_bf16(sacc[0], aH, bL);
            mma_bf16(sacc[1], aH, bL + 2);
            mma_bf16(sacc[0], aL, bH);
            mma_bf16(sacc[1], aL, bH + 2);
        }

        // ---- causal mask
        #pragma unroll
        for (int nb = 0; nb < 2; nb++) {
            int c = s0 + 16 * wc + 8 * nb + 2 * lt;
            if (c     > r0g) sacc[nb][0] = -3.0e38f;
            if (c + 1 > r0g) sacc[nb][1] = -3.0e38f;
            if (c     > r1g) sacc[nb][2] = -3.0e38f;
            if (c + 1 > r1g) sacc[nb][3] = -3.0e38f;
        }

        // ---- half row max (quad shuffle), exchange across halves
        float mx0 = fmaxf(fmaxf(sacc[0][0], sacc[0][1]), fmaxf(sacc[1][0], sacc[1][1]));
        float mx1 = fmaxf(fmaxf(sacc[0][2], sacc[0][3]), fmaxf(sacc[1][2], sacc[1][3]));
        mx0 = fmaxf(mx0, __shfl_xor_sync(0xffffffff, mx0, 1));
        mx0 = fmaxf(mx0, __shfl_xor_sync(0xffffffff, mx0, 2));
        mx1 = fmaxf(mx1, __shfl_xor_sync(0xffffffff, mx1, 1));
        mx1 = fmaxf(mx1, __shfl_xor_sync(0xffffffff, mx1, 2));
        if (lt == 0) {
            redm[wc * 64 + r0l] = mx0;
            redm[wc * 64 + r1l] = mx1;
        }
        __syncthreads();                               // sync B: maxes visible
        float mn0 = fmaxf(m0v, fmaxf(mx0, redm[(1 - wc) * 64 + r0l]));
        float mn1 = fmaxf(m1v, fmaxf(mx1, redm[(1 - wc) * 64 + r1l]));
        float al0 = __expf(m0v - mn0);
        float al1 = __expf(m1v - mn1);
        m0v = mn0; m1v = mn1;

        // ---- P = exp(S - m) -> smem (hi/lo), partial sums
        float ps0 = 0.f, ps1 = 0.f;
        #pragma unroll
        for (int nb = 0; nb < 2; nb++) {
            float e0 = __expf(sacc[nb][0] - mn0);
            float e1 = __expf(sacc[nb][1] - mn0);
            float e2 = __expf(sacc[nb][2] - mn1);
            float e3 = __expf(sacc[nb][3] - mn1);
            ps0 += e0 + e1;
            ps1 += e2 + e3;
            int cb = (16 * wc + 8 * nb + 2 * lt) * 2;  // byte col offset
            uint32_t hw, lw;
            split2(e0, e1, hw, lw);
            *(uint32_t*)(smp + A_PHI + r0l * PSTRB + cb) = hw;
            *(uint32_t*)(smp + A_PLO + r0l * PSTRB + cb) = lw;
            split2(e2, e3, hw, lw);
            *(uint32_t*)(smp + A_PHI + r1l * PSTRB + cb) = hw;
            *(uint32_t*)(smp + A_PLO + r1l * PSTRB + cb) = lw;
        }
        ps0 += __shfl_xor_sync(0xffffffff, ps0, 1);
        ps0 += __shfl_xor_sync(0xffffffff, ps0, 2);
        ps1 += __shfl_xor_sync(0xffffffff, ps1, 1);
        ps1 += __shfl_xor_sync(0xffffffff, ps1, 2);
        if (lt == 0) {
            reds[wc * 64 + r0l] = ps0;
            reds[wc * 64 + r1l] = ps1;
        }
        __syncthreads();                               // sync C: P + sums visible
        l0v = l0v * al0 + reds[r0l] + reds[64 + r0l];
        l1v = l1v * al1 + reds[r1l] + reds[64 + r1l];

        // ---- O rescale
        #pragma unroll
        for (int nb = 0; nb < 16; nb++) {
            oacc[nb][0] *= al0; oacc[nb][1] *= al0;
            oacc[nb][2] *= al1; oacc[nb][3] *= al1;
        }

        // ---- prefetch next tile (all warps past previous tile: safe)
        if (it + 1 < ntiles) {
            attn_issue(sb + A_BUF0 + ((it + 1) & 1) * A_BUFSZ, kh, kl, vh, vl,
                       (it + 1) * TSA, t);
            CP_COMMIT();
        }

        // ---- PV: O += Phi*Vhi + Phi*Vlo + Plo*Vhi (16 rows x 128 cols)
        #pragma unroll
        for (int ks = 0; ks < 2; ks++) {
            uint32_t aH[4], aL[4];
            uint32_t pa = sb + A_PHI + (16 * wr + (l & 15)) * PSTRB
                        + (16 * ks + ((l >> 4) << 3)) * 2;
            ldmx4(aH, pa);
            ldmx4(aL, pa + (A_PLO - A_PHI));
            #pragma unroll
            for (int hb = 0; hb < 8; hb++) {
                uint32_t va = B + T_VH
                            + (16 * ks + (l & 7) + (((l >> 3) & 1) << 3)) * QROW_B
                            + (128 * wc + 16 * hb + ((l >> 4) << 3)) * 2;
                uint32_t bH[4], bL[4];
                ldmx4t(bH, va);
                ldmx4t(bL, va + (T_VL - T_VH));
                mma_bf16(oacc[2 * hb],     aH, bH);
                mma_bf16(oacc[2 * hb + 1], aH, bH + 2);
                mma_bf16(oacc[2 * hb],     aH, bL);
                mma_bf16(oacc[2 * hb + 1], aH, bL + 2);
                mma_bf16(oacc[2 * hb],     aL, bH);
                mma_bf16(oacc[2 * hb + 1], aL, bH + 2);
            }
        }
    }

    // ---- epilogue: out = O / l
    {
        float inv0 = 1.0f / l0v;
        float inv1 = 1.0f / l1v;
        float* o0 = out + ((size_t)b * NT + r0g) * NH;
        float* o1 = out + ((size_t)b * NT + r1g) * NH;
        #pragma unroll
        for (int nb = 0; nb < 16; nb++) {
            int col = 128 * wc + 8 * nb + 2 * lt;
            *(float2*)&o0[col] = make_float2(oacc[nb][0] * inv0, oacc[nb][1] * inv0);
            *(float2*)&o1[col] = make_float2(oacc[nb][2] * inv1, oacc[nb][3] * inv1);
        }
    }
}

// ---------------------------------------------------------------------------
extern "C" void kernel_launch(void* const* d_in, const int* in_sizes, int n_in,
                              void* d_out, int out_size)
{
    const float* x  = (const float*)d_in[0];
    const float* Wq = (const float*)d_in[1];
    const float* Wk = (const float*)d_in[2];
    const float* Wv = (const float*)d_in[3];
    float* out = (float*)d_out;

    cudaFuncSetAttribute(qkv_gemm_kernel,
                         cudaFuncAttributeMaxDynamicSharedMemorySize, GEMM_SMEM);
    cudaFuncSetAttribute(attn_mma_kernel,
                         cudaFuncAttributeMaxDynamicSharedMemorySize, ATTN_SMEM);

    convert_x_kernel<<<16384, 256>>>(x);
    convert_w_kernel<<<768, 256>>>(Wq, Wk, Wv);
    qkv_gemm_kernel<<<dim3(2, (NB * NT) / 128, 3), 256, GEMM_SMEM>>>();
    attn_mma_kernel<<<dim3(NT / 64, NB), 256, ATTN_SMEM>>>(out);
}